// round 16
// baseline (speedup 1.0000x reference)
#include <cuda_runtime.h>
#include <cuda_fp16.h>
#include <math.h>
#include <stdint.h>

#define N_NODES 10000
#define N_RELS  200
#define DIM     128
#define VIS_DIM 512
#define TXT_DIM 768
#define N_EDGES 320000
#define MAXDEG  128

typedef unsigned long long ull;

// ---------------- scratch (static __device__, no allocs) ----------------
__device__ __half g_vf16[N_NODES * DIM];
__device__ __half g_tf16[N_NODES * DIM];

__device__ float  g_A[3][N_NODES * DIM];    // dst-side tables (fp32)
__device__ float  g_Bf[3][N_NODES * DIM];   // src-side tables (fp32, gathered per edge)
__device__ float  g_Rf[3][N_RELS * DIM];    // relation tables (fp32, L2-resident)
__device__ float4 g_asc4[N_NODES];          // packed w2.A per conv
__device__ float4 g_bsc4[N_NODES];          // packed w2.B per conv
__device__ float4 g_rsc4[N_RELS];           // packed w2.R per conv
__device__ float4 g_ew[N_NODES * MAXDEG];   // precomputed exp weights per edge (e0,e1,e2,-)
__device__ int    g_counts[N_NODES];        // zero-initialized; aggregate resets after use
__device__ int    g_bucket[N_NODES * MAXDEG];   // packed: src | (et << 16)

__device__ __forceinline__ float lrelu(float x) { return x > 0.f ? x : 0.01f * x; }

__device__ __forceinline__ void ffma2(ull& d, ull a, ull b) {
    asm("fma.rn.f32x2 %0, %1, %2, %3;" : "=l"(d) : "l"(a), "l"(b), "l"(d));
}
__device__ __forceinline__ ull fadd2(ull a, ull b) {
    ull d;
    asm("add.rn.f32x2 %0, %1, %2;" : "=l"(d) : "l"(a), "l"(b));
    return d;
}

// ---------------- bucket scatter: standalone, lightweight, full occupancy ----------------
__global__ void scatter_kernel(const int* __restrict__ src,
                               const int* __restrict__ dst,
                               const int* __restrict__ et) {
    int e0 = (blockIdx.x * blockDim.x + threadIdx.x) * 2;
    if (e0 >= N_EDGES) return;
    int2 d2 = *(const int2*)(dst + e0);
    int2 s2 = *(const int2*)(src + e0);
    int2 t2 = *(const int2*)(et + e0);
    int slot0 = atomicAdd(&g_counts[d2.x], 1);
    if (slot0 < MAXDEG) g_bucket[d2.x * MAXDEG + slot0] = s2.x | (t2.x << 16);
    int slot1 = atomicAdd(&g_counts[d2.y], 1);
    if (slot1 < MAXDEG) g_bucket[d2.y * MAXDEG + slot1] = s2.y | (t2.y << 16);
}

// ---------------- dtype-polymorphic 16-half loader (fp16 passthrough / fp32 convert) ----
__device__ __forceinline__ uint32_t pack2(float x, float y) {
    __half2 h = __floats2half2_rn(x, y);
    return *(uint32_t*)&h;
}
__device__ __forceinline__ void load16(const __half* p, uint4& a, uint4& b) {
    a = ((const uint4*)p)[0];
    b = ((const uint4*)p)[1];
}
__device__ __forceinline__ void load16(const float* p, uint4& a, uint4& b) {
    float4 f0 = ((const float4*)p)[0];
    float4 f1 = ((const float4*)p)[1];
    float4 f2 = ((const float4*)p)[2];
    float4 f3 = ((const float4*)p)[3];
    a.x = pack2(f0.x, f0.y); a.y = pack2(f0.z, f0.w);
    a.z = pack2(f1.x, f1.y); a.w = pack2(f1.z, f1.w);
    b.x = pack2(f2.x, f2.y); b.y = pack2(f2.z, f2.w);
    b.z = pack2(f3.x, f3.y); b.w = pack2(f3.z, f3.w);
}

// ---------------- tensor-core GEMM tile ----------------
#define MBK 32
#define XS  40    // padded smem row stride (halves)

__device__ __forceinline__ void ldm4(uint32_t& r0, uint32_t& r1, uint32_t& r2, uint32_t& r3,
                                     const __half* p) {
    uint32_t addr = (uint32_t)__cvta_generic_to_shared(p);
    asm volatile("ldmatrix.sync.aligned.m8n8.x4.shared.b16 {%0,%1,%2,%3}, [%4];"
                 : "=r"(r0), "=r"(r1), "=r"(r2), "=r"(r3) : "r"(addr));
}

__device__ __forceinline__ void mma16816(float* d, const uint32_t* a, uint32_t b0, uint32_t b1) {
    asm volatile("mma.sync.aligned.m16n8k16.row.col.f32.f16.f16.f32 "
                 "{%0,%1,%2,%3}, {%4,%5,%6,%7}, {%8,%9}, {%0,%1,%2,%3};"
                 : "+f"(d[0]), "+f"(d[1]), "+f"(d[2]), "+f"(d[3])
                 : "r"(a[0]), "r"(a[1]), "r"(a[2]), "r"(a[3]), "r"(b0), "r"(b1));
}

// C[row0:row0+128, 0:128] = X[M x K] @ W[128 x K]^T (+bias)
// outputs: optional fp32 Cf, optional fp16 Ch; optional rowdot sc[row*scstride] = w2 . row
template <class TX, class TW>
__device__ __forceinline__
void mma_tile(const TX* __restrict__ X, int M, int K, int ldx,
              const TW* __restrict__ W, int ldw,
              const float* __restrict__ bias,
              float* __restrict__ Cf, __half* __restrict__ Ch,
              const float* __restrict__ w2, float* __restrict__ sc, int scstride,
              int row0) {
    __shared__ __half sx[128 * XS];
    __shared__ __half sw[128 * XS];
    __shared__ float scbuf[128];

    int tid = threadIdx.x;
    int lane = tid & 31;
    int warp = tid >> 5;
    int wm = warp & 1;
    int wn = warp >> 1;

    int lrow = tid >> 1;
    int lcol = (tid & 1) * 16;

    float acc[4][4][4];
#pragma unroll
    for (int i = 0; i < 4; i++)
#pragma unroll
        for (int j = 0; j < 4; j++)
#pragma unroll
            for (int q = 0; q < 4; q++) acc[i][j][q] = 0.f;

    int rm = row0 + lrow; if (rm > M - 1) rm = M - 1;
    const TX* xp = X + (size_t)rm * ldx + lcol;
    const TW* wp = W + (size_t)lrow * ldw + lcol;

    uint4 px0, px1, pw0, pw1;
    load16(xp, px0, px1);
    load16(wp, pw0, pw1);

    int niter = K / MBK;
    for (int it = 0; it < niter; it++) {
        ((uint4*)(sx + lrow * XS + lcol))[0] = px0;
        ((uint4*)(sx + lrow * XS + lcol))[1] = px1;
        ((uint4*)(sw + lrow * XS + lcol))[0] = pw0;
        ((uint4*)(sw + lrow * XS + lcol))[1] = pw1;
        __syncthreads();

        if (it + 1 < niter) {
            int k0 = (it + 1) * MBK;
            load16(xp + k0, px0, px1);
            load16(wp + k0, pw0, pw1);
        }

#pragma unroll
        for (int ks = 0; ks < 2; ks++) {
            int k0 = ks * 16;
            uint32_t af[4][4];
#pragma unroll
            for (int mt = 0; mt < 4; mt++) {
                const __half* p = sx + (wm * 64 + mt * 16 + (lane & 15)) * XS
                                  + k0 + (lane >> 4) * 8;
                ldm4(af[mt][0], af[mt][1], af[mt][2], af[mt][3], p);
            }
            uint32_t bf[2][4];
#pragma unroll
            for (int bt = 0; bt < 2; bt++) {
                int nrow = wn * 32 + bt * 16 + (lane & 7) + ((lane >> 4) << 3);
                const __half* p = sw + nrow * XS + k0 + ((lane >> 3) & 1) * 8;
                ldm4(bf[bt][0], bf[bt][1], bf[bt][2], bf[bt][3], p);
            }
#pragma unroll
            for (int mt = 0; mt < 4; mt++)
#pragma unroll
                for (int nt = 0; nt < 4; nt++)
                    mma16816(acc[mt][nt], af[mt],
                             bf[nt >> 1][(nt & 1) * 2], bf[nt >> 1][(nt & 1) * 2 + 1]);
        }
        __syncthreads();
    }

    int gid = lane >> 2, tig = lane & 3;

    if (bias) {
#pragma unroll
        for (int nt = 0; nt < 4; nt++) {
            int col = wn * 32 + nt * 8 + tig * 2;
            float w0 = bias[col], w1 = bias[col + 1];
#pragma unroll
            for (int mt = 0; mt < 4; mt++) {
                acc[mt][nt][0] += w0; acc[mt][nt][1] += w1;
                acc[mt][nt][2] += w0; acc[mt][nt][3] += w1;
            }
        }
    }

    if (w2) {
        if (tid < 128) scbuf[tid] = 0.f;
        __syncthreads();
        float w2v[8];
#pragma unroll
        for (int nt = 0; nt < 4; nt++) {
            int col = wn * 32 + nt * 8 + tig * 2;
            w2v[2 * nt] = w2[col]; w2v[2 * nt + 1] = w2[col + 1];
        }
#pragma unroll
        for (int mt = 0; mt < 4; mt++) {
            float s1 = 0.f, s2 = 0.f;
#pragma unroll
            for (int nt = 0; nt < 4; nt++) {
                s1 += acc[mt][nt][0] * w2v[2 * nt] + acc[mt][nt][1] * w2v[2 * nt + 1];
                s2 += acc[mt][nt][2] * w2v[2 * nt] + acc[mt][nt][3] * w2v[2 * nt + 1];
            }
            s1 += __shfl_xor_sync(0xffffffffu, s1, 1);
            s1 += __shfl_xor_sync(0xffffffffu, s1, 2);
            s2 += __shfl_xor_sync(0xffffffffu, s2, 1);
            s2 += __shfl_xor_sync(0xffffffffu, s2, 2);
            if (tig == 0) {
                atomicAdd(&scbuf[wm * 64 + mt * 16 + gid], s1);
                atomicAdd(&scbuf[wm * 64 + mt * 16 + gid + 8], s2);
            }
        }
        __syncthreads();
        if (tid < 128 && row0 + tid < M) sc[(size_t)(row0 + tid) * scstride] = scbuf[tid];
    }

#pragma unroll
    for (int mt = 0; mt < 4; mt++) {
        int r1 = row0 + wm * 64 + mt * 16 + gid;
        int r2 = r1 + 8;
#pragma unroll
        for (int nt = 0; nt < 4; nt++) {
            int col = wn * 32 + nt * 8 + tig * 2;
            float c0 = acc[mt][nt][0], c1 = acc[mt][nt][1];
            float c2 = acc[mt][nt][2], c3 = acc[mt][nt][3];
            if (Cf) {
                if (r1 < M) *(float2*)(Cf + (size_t)r1 * DIM + col) = make_float2(c0, c1);
                if (r2 < M) *(float2*)(Cf + (size_t)r2 * DIM + col) = make_float2(c2, c3);
            }
            if (Ch) {
                if (r1 < M) *(__half2*)(Ch + (size_t)r1 * DIM + col) = __floats2half2_rn(c0, c1);
                if (r2 < M) *(__half2*)(Ch + (size_t)r2 * DIM + col) = __floats2half2_rn(c2, c3);
            }
        }
    }
}

#define GBN ((N_NODES + 127) / 128)

// ---- modality projections (fp32 inputs, fp16 out), convert fused into loads ----
__global__ __launch_bounds__(256, 2)
void proj_mma_kernel(const float* __restrict__ vis, const float* __restrict__ Wv,
                     const float* __restrict__ bv,
                     const float* __restrict__ txt, const float* __restrict__ Wt,
                     const float* __restrict__ bt) {
    int row0 = blockIdx.x * 128;
    if (blockIdx.z == 0)
        mma_tile<float, float>(vis, N_NODES, VIS_DIM, VIS_DIM, Wv, VIS_DIM, bv,
                               nullptr, g_vf16, nullptr, nullptr, 0, row0);
    else
        mma_tile<float, float>(txt, N_NODES, TXT_DIM, TXT_DIM, Wt, TXT_DIM, bt,
                               nullptr, g_tf16, nullptr, nullptr, 0, row0);
}

// ---- node tables (z=0..5) + relation tables (z=6); B and R now fp32 outputs ----
__global__ __launch_bounds__(256, 2)
void node_rel_kernel(const float* __restrict__ s_emb, const float* __restrict__ rel_emb,
                     const float* __restrict__ W1s, const float* __restrict__ b1s,
                     const float* __restrict__ w2s,
                     const float* __restrict__ W1v, const float* __restrict__ b1v,
                     const float* __restrict__ w2v,
                     const float* __restrict__ W1t, const float* __restrict__ b1t,
                     const float* __restrict__ w2t) {
    int z = blockIdx.z;
    if (z < 6) {
        int c = z >> 1;          // conv
        int half = z & 1;        // 0=A(dst) 1=B(src)
        const float* W1 = (c == 0) ? W1s : (c == 1) ? W1v : W1t;
        const float* w2 = (c == 0) ? w2s : (c == 1) ? w2v : w2t;
        int row0 = blockIdx.x * 128;
        if (c == 0) {
            if (half == 0)
                mma_tile<float, float>(s_emb, N_NODES, DIM, DIM, W1, 384, nullptr,
                                       g_A[0], nullptr, w2, (float*)g_asc4 + 0, 4, row0);
            else
                mma_tile<float, float>(s_emb, N_NODES, DIM, DIM, W1 + 128, 384, nullptr,
                                       g_Bf[0], nullptr, w2, (float*)g_bsc4 + 0, 4, row0);
        } else {
            const __half* feat = (c == 1) ? g_vf16 : g_tf16;
            if (half == 0)
                mma_tile<__half, float>(feat, N_NODES, DIM, DIM, W1, 384, nullptr,
                                        g_A[c], nullptr, w2, (float*)g_asc4 + c, 4, row0);
            else
                mma_tile<__half, float>(feat, N_NODES, DIM, DIM, W1 + 128, 384, nullptr,
                                        g_Bf[c], nullptr, w2, (float*)g_bsc4 + c, 4, row0);
        }
    } else {
        if (blockIdx.x >= 6) return;
        int c = blockIdx.x >> 1;
        int row0 = (blockIdx.x & 1) * 128;
        const float* W1 = (c == 0) ? W1s : (c == 1) ? W1v : W1t;
        const float* b1 = (c == 0) ? b1s : (c == 1) ? b1v : b1t;
        const float* w2 = (c == 0) ? w2s : (c == 1) ? w2v : w2t;
        mma_tile<float, float>(rel_emb, N_RELS, DIM, DIM, W1 + 256, 384, b1,
                               g_Rf[c], nullptr, w2, (float*)g_rsc4 + c, 4, row0);
    }
}

// ---------------- logit precompute: 1 thread per bucket slot ----------------
__global__ void logit_kernel() {
    int tid = blockIdx.x * blockDim.x + threadIdx.x;
    int n = tid >> 7;              // / MAXDEG
    int slot = tid & (MAXDEG - 1);
    if (n >= N_NODES) return;
    int cnt = g_counts[n];
    if (cnt > MAXDEG) cnt = MAXDEG;
    if (slot >= cnt) return;
    int pk = g_bucket[n * MAXDEG + slot];
    int s = pk & 0xFFFF;
    int t = pk >> 16;
    float4 av = g_asc4[n];
    float4 bs = g_bsc4[s];
    float4 rs = g_rsc4[t];
    float4 ew;
    ew.x = __expf(lrelu(av.x + bs.x + rs.x));
    ew.y = __expf(lrelu(av.y + bs.y + rs.y));
    ew.z = __expf(lrelu(av.z + bs.z + rs.z));
    ew.w = 0.f;
    g_ew[n * MAXDEG + slot] = ew;
}

// ---------------- fused aggregation: half-warp pairing + precomputed weights + f32x2 ----
__global__ __launch_bounds__(256)
void aggregate_kernel(const float* __restrict__ alpha_p,
                      const float* __restrict__ gamma_p,
                      float* __restrict__ out) {
    int gw = (blockIdx.x * blockDim.x + threadIdx.x) >> 5;   // node id
    int lane = threadIdx.x & 31;
    if (gw >= N_NODES) return;

    int cnt = g_counts[gw];
    if (lane == 0) g_counts[gw] = 0;       // restore invariant for next replay
    if (cnt > MAXDEG) cnt = MAXDEG;
    const int* bucket = g_bucket + (size_t)gw * MAXDEG;
    const float4* ewp = g_ew + (size_t)gw * MAXDEG;

    int hw = lane >> 4;        // which edge of the pair
    int hl = lane & 15;        // position within half-warp
    int loff = hl * 8;         // 8 floats per lane

    const float* B0 = g_Bf[0];
    const float* B1 = g_Bf[1];
    const float* B2 = g_Bf[2];
    const float* R0 = g_Rf[0];
    const float* R1 = g_Rf[1];
    const float* R2 = g_Rf[2];

    ull acc0[4] = {0, 0, 0, 0};
    ull acc1[4] = {0, 0, 0, 0};
    ull acc2[4] = {0, 0, 0, 0};
    float z0 = 0.f, z1 = 0.f, z2 = 0.f;

#pragma unroll 2
    for (int i = 0; i < cnt; i += 2) {
        int ei = i + hw;
        bool valid = (ei < cnt);
        int idx = valid ? ei : i;
        int pk = bucket[idx];
        float4 ew = ewp[idx];
        int s = pk & 0xFFFF;
        int t = pk >> 16;
        float vm = valid ? 1.f : 0.f;

        float e0 = vm * ew.x, e1 = vm * ew.y, e2 = vm * ew.z;
        z0 += e0; z1 += e1; z2 += e2;
        float2 e0f = {e0, e0}, e1f = {e1, e1}, e2f = {e2, e2};
        ull ep0 = *(ull*)&e0f, ep1 = *(ull*)&e1f, ep2 = *(ull*)&e2f;

        const float* pb0 = B0 + s * DIM + loff;
        const float* pr0 = R0 + t * DIM + loff;
        const float* pb1 = B1 + s * DIM + loff;
        const float* pr1 = R1 + t * DIM + loff;
        const float* pb2 = B2 + s * DIM + loff;
        const float* pr2 = R2 + t * DIM + loff;
        ulonglong2 b0a = ((const ulonglong2*)pb0)[0], b0b = ((const ulonglong2*)pb0)[1];
        ulonglong2 r0a = ((const ulonglong2*)pr0)[0], r0b = ((const ulonglong2*)pr0)[1];
        ulonglong2 b1a = ((const ulonglong2*)pb1)[0], b1b = ((const ulonglong2*)pb1)[1];
        ulonglong2 r1a = ((const ulonglong2*)pr1)[0], r1b = ((const ulonglong2*)pr1)[1];
        ulonglong2 b2a = ((const ulonglong2*)pb2)[0], b2b = ((const ulonglong2*)pb2)[1];
        ulonglong2 r2a = ((const ulonglong2*)pr2)[0], r2b = ((const ulonglong2*)pr2)[1];

        ffma2(acc0[0], fadd2(b0a.x, r0a.x), ep0);
        ffma2(acc0[1], fadd2(b0a.y, r0a.y), ep0);
        ffma2(acc0[2], fadd2(b0b.x, r0b.x), ep0);
        ffma2(acc0[3], fadd2(b0b.y, r0b.y), ep0);
        ffma2(acc1[0], fadd2(b1a.x, r1a.x), ep1);
        ffma2(acc1[1], fadd2(b1a.y, r1a.y), ep1);
        ffma2(acc1[2], fadd2(b1b.x, r1b.x), ep1);
        ffma2(acc1[3], fadd2(b1b.y, r1b.y), ep1);
        ffma2(acc2[0], fadd2(b2a.x, r2a.x), ep2);
        ffma2(acc2[1], fadd2(b2a.y, r2a.y), ep2);
        ffma2(acc2[2], fadd2(b2b.x, r2b.x), ep2);
        ffma2(acc2[3], fadd2(b2b.y, r2b.y), ep2);
    }

    // unpack to scalar accumulators
    float a0f[8], a1f[8], a2f[8];
#pragma unroll
    for (int k = 0; k < 4; k++) {
        float2 p;
        p = *(float2*)&acc0[k]; a0f[2 * k] = p.x; a0f[2 * k + 1] = p.y;
        p = *(float2*)&acc1[k]; a1f[2 * k] = p.x; a1f[2 * k + 1] = p.y;
        p = *(float2*)&acc2[k]; a2f[2 * k] = p.x; a2f[2 * k + 1] = p.y;
    }

    // combine the two half-warps (each covered the same dims, different edges)
#pragma unroll
    for (int k = 0; k < 8; k++) {
        a0f[k] += __shfl_xor_sync(0xffffffffu, a0f[k], 16);
        a1f[k] += __shfl_xor_sync(0xffffffffu, a1f[k], 16);
        a2f[k] += __shfl_xor_sync(0xffffffffu, a2f[k], 16);
    }
    z0 += __shfl_xor_sync(0xffffffffu, z0, 16);
    z1 += __shfl_xor_sync(0xffffffffu, z1, 16);
    z2 += __shfl_xor_sync(0xffffffffu, z2, 16);

    float al = *alpha_p, ga = *gamma_p;
    float cs = 1.f - al - ga;
    int col = hl * 8 + hw * 4;           // this lane writes 4 dims
    int base = hw * 4;                   // which 4 of the lane's 8 accumulated dims
    float4 o = {0, 0, 0, 0};
    if (cnt > 0) {
        float4 A0 = *(const float4*)(&g_A[0][gw * DIM + col]);
        float4 A1 = *(const float4*)(&g_A[1][gw * DIM + col]);
        float4 A2 = *(const float4*)(&g_A[2][gw * DIM + col]);
        float iz0 = 1.f / z0, iz1 = 1.f / z1, iz2 = 1.f / z2;
        o.x = cs * lrelu(A0.x + a0f[base + 0] * iz0) + al * lrelu(A1.x + a1f[base + 0] * iz1) + ga * lrelu(A2.x + a2f[base + 0] * iz2);
        o.y = cs * lrelu(A0.y + a0f[base + 1] * iz0) + al * lrelu(A1.y + a1f[base + 1] * iz1) + ga * lrelu(A2.y + a2f[base + 1] * iz2);
        o.z = cs * lrelu(A0.z + a0f[base + 2] * iz0) + al * lrelu(A1.z + a1f[base + 2] * iz1) + ga * lrelu(A2.z + a2f[base + 2] * iz2);
        o.w = cs * lrelu(A0.w + a0f[base + 3] * iz0) + al * lrelu(A1.w + a1f[base + 3] * iz1) + ga * lrelu(A2.w + a2f[base + 3] * iz2);
    }
    *(float4*)(out + (size_t)gw * DIM + col) = o;
}

// ---------------- host launcher ----------------
extern "C" void kernel_launch(void* const* d_in, const int* in_sizes, int n_in,
                              void* d_out, int out_size) {
    const int*   edge_index = (const int*)d_in[1];   // [2, E]
    const int*   edge_type  = (const int*)d_in[2];
    const float* visual     = (const float*)d_in[3];
    const float* textual    = (const float*)d_in[4];
    const float* s_emb      = (const float*)d_in[5];
    const float* rel_emb    = (const float*)d_in[6];
    const float* W1_s = (const float*)d_in[7];
    const float* b1_s = (const float*)d_in[8];
    const float* w2_s = (const float*)d_in[9];
    const float* W1_v = (const float*)d_in[10];
    const float* b1_v = (const float*)d_in[11];
    const float* w2_v = (const float*)d_in[12];
    const float* W1_t = (const float*)d_in[13];
    const float* b1_t = (const float*)d_in[14];
    const float* w2_t = (const float*)d_in[15];
    const float* Wv = (const float*)d_in[16];
    const float* bv = (const float*)d_in[17];
    const float* Wt = (const float*)d_in[18];
    const float* bt = (const float*)d_in[19];
    const float* alpha = (const float*)d_in[20];
    const float* gamma = (const float*)d_in[21];
    float* out = (float*)d_out;

    const int* src = edge_index;
    const int* dst = edge_index + N_EDGES;

    // launch 0: bucket scatter (lightweight, full occupancy)
    scatter_kernel<<<(N_EDGES / 2 + 255) / 256, 256>>>(src, dst, edge_type);

    // launch 1: modality projections (fp32 inputs converted in-register)
    proj_mma_kernel<<<dim3(GBN, 1, 2), 256>>>(visual, Wv, bv, textual, Wt, bt);

    // launch 2: node tables (z=0..5) + relation tables (z=6)
    node_rel_kernel<<<dim3(GBN, 1, 7), 256>>>(
        s_emb, rel_emb, W1_s, b1_s, w2_s, W1_v, b1_v, w2_v, W1_t, b1_t, w2_t);

    // launch 3: per-edge logit/exp precompute (1 thread per bucket slot)
    logit_kernel<<<(N_NODES * MAXDEG) / 256, 256>>>();

    // launch 4: fused aggregation, 1 warp per node, half-warp pairing, f32x2 math
    aggregate_kernel<<<1250, 256>>>(alpha, gamma, out);
}

// round 17
// speedup vs baseline: 1.2984x; 1.2984x over previous
#include <cuda_runtime.h>
#include <cuda_fp16.h>
#include <math.h>
#include <stdint.h>

#define N_NODES 10000
#define N_RELS  200
#define DIM     128
#define VIS_DIM 512
#define TXT_DIM 768
#define N_EDGES 320000
#define MAXDEG  128

// ---------------- scratch (static __device__, no allocs) ----------------
__device__ __half g_vf16[N_NODES * DIM];
__device__ __half g_tf16[N_NODES * DIM];

__device__ float  g_A[3][N_NODES * DIM];    // dst-side tables (fp32, read once per node)
__device__ __half g_Bh[3][N_NODES * DIM];   // src-side tables (fp16, gathered per edge)
__device__ __half g_Rh[3][N_RELS * DIM];    // relation tables (fp16, L1/L2 resident)
__device__ float4 g_asc4[N_NODES];          // packed w2.A per conv
__device__ float4 g_bsc4[N_NODES];          // packed w2.B per conv
__device__ float4 g_rsc4[N_RELS];           // packed w2.R per conv
__device__ int    g_counts[N_NODES];        // zero-initialized; aggregate resets after use
__device__ int    g_bucket[N_NODES * MAXDEG];   // packed: src | (et << 16)

__device__ __forceinline__ float lrelu(float x) { return x > 0.f ? x : 0.01f * x; }

// ---------------- bucket scatter: standalone, lightweight, full occupancy ----------------
__global__ void scatter_kernel(const int* __restrict__ src,
                               const int* __restrict__ dst,
                               const int* __restrict__ et) {
    int e0 = (blockIdx.x * blockDim.x + threadIdx.x) * 2;
    if (e0 >= N_EDGES) return;
    int2 d2 = *(const int2*)(dst + e0);
    int2 s2 = *(const int2*)(src + e0);
    int2 t2 = *(const int2*)(et + e0);
    int slot0 = atomicAdd(&g_counts[d2.x], 1);
    if (slot0 < MAXDEG) g_bucket[d2.x * MAXDEG + slot0] = s2.x | (t2.x << 16);
    int slot1 = atomicAdd(&g_counts[d2.y], 1);
    if (slot1 < MAXDEG) g_bucket[d2.y * MAXDEG + slot1] = s2.y | (t2.y << 16);
}

// ---------------- dtype-polymorphic 16-half loader (fp16 passthrough / fp32 convert) ----
__device__ __forceinline__ uint32_t pack2(float x, float y) {
    __half2 h = __floats2half2_rn(x, y);
    return *(uint32_t*)&h;
}
__device__ __forceinline__ void load16(const __half* p, uint4& a, uint4& b) {
    a = ((const uint4*)p)[0];
    b = ((const uint4*)p)[1];
}
__device__ __forceinline__ void load16(const float* p, uint4& a, uint4& b) {
    float4 f0 = ((const float4*)p)[0];
    float4 f1 = ((const float4*)p)[1];
    float4 f2 = ((const float4*)p)[2];
    float4 f3 = ((const float4*)p)[3];
    a.x = pack2(f0.x, f0.y); a.y = pack2(f0.z, f0.w);
    a.z = pack2(f1.x, f1.y); a.w = pack2(f1.z, f1.w);
    b.x = pack2(f2.x, f2.y); b.y = pack2(f2.z, f2.w);
    b.z = pack2(f3.x, f3.y); b.w = pack2(f3.z, f3.w);
}

// ---------------- tensor-core GEMM tile ----------------
#define MBK 32
#define XS  40    // padded smem row stride (halves)

__device__ __forceinline__ void ldm4(uint32_t& r0, uint32_t& r1, uint32_t& r2, uint32_t& r3,
                                     const __half* p) {
    uint32_t addr = (uint32_t)__cvta_generic_to_shared(p);
    asm volatile("ldmatrix.sync.aligned.m8n8.x4.shared.b16 {%0,%1,%2,%3}, [%4];"
                 : "=r"(r0), "=r"(r1), "=r"(r2), "=r"(r3) : "r"(addr));
}

__device__ __forceinline__ void mma16816(float* d, const uint32_t* a, uint32_t b0, uint32_t b1) {
    asm volatile("mma.sync.aligned.m16n8k16.row.col.f32.f16.f16.f32 "
                 "{%0,%1,%2,%3}, {%4,%5,%6,%7}, {%8,%9}, {%0,%1,%2,%3};"
                 : "+f"(d[0]), "+f"(d[1]), "+f"(d[2]), "+f"(d[3])
                 : "r"(a[0]), "r"(a[1]), "r"(a[2]), "r"(a[3]), "r"(b0), "r"(b1));
}

// C[row0:row0+128, 0:128] = X[M x K] @ W[128 x K]^T (+bias)
// outputs: optional fp32 Cf, optional fp16 Ch; optional rowdot sc[row*scstride] = w2 . row
template <class TX, class TW>
__device__ __forceinline__
void mma_tile(const TX* __restrict__ X, int M, int K, int ldx,
              const TW* __restrict__ W, int ldw,
              const float* __restrict__ bias,
              float* __restrict__ Cf, __half* __restrict__ Ch,
              const float* __restrict__ w2, float* __restrict__ sc, int scstride,
              int row0) {
    __shared__ __half sx[128 * XS];
    __shared__ __half sw[128 * XS];
    __shared__ float scbuf[128];

    int tid = threadIdx.x;
    int lane = tid & 31;
    int warp = tid >> 5;
    int wm = warp & 1;
    int wn = warp >> 1;

    int lrow = tid >> 1;
    int lcol = (tid & 1) * 16;

    float acc[4][4][4];
#pragma unroll
    for (int i = 0; i < 4; i++)
#pragma unroll
        for (int j = 0; j < 4; j++)
#pragma unroll
            for (int q = 0; q < 4; q++) acc[i][j][q] = 0.f;

    int rm = row0 + lrow; if (rm > M - 1) rm = M - 1;
    const TX* xp = X + (size_t)rm * ldx + lcol;
    const TW* wp = W + (size_t)lrow * ldw + lcol;

    uint4 px0, px1, pw0, pw1;
    load16(xp, px0, px1);
    load16(wp, pw0, pw1);

    int niter = K / MBK;
    for (int it = 0; it < niter; it++) {
        ((uint4*)(sx + lrow * XS + lcol))[0] = px0;
        ((uint4*)(sx + lrow * XS + lcol))[1] = px1;
        ((uint4*)(sw + lrow * XS + lcol))[0] = pw0;
        ((uint4*)(sw + lrow * XS + lcol))[1] = pw1;
        __syncthreads();

        if (it + 1 < niter) {
            int k0 = (it + 1) * MBK;
            load16(xp + k0, px0, px1);
            load16(wp + k0, pw0, pw1);
        }

#pragma unroll
        for (int ks = 0; ks < 2; ks++) {
            int k0 = ks * 16;
            uint32_t af[4][4];
#pragma unroll
            for (int mt = 0; mt < 4; mt++) {
                const __half* p = sx + (wm * 64 + mt * 16 + (lane & 15)) * XS
                                  + k0 + (lane >> 4) * 8;
                ldm4(af[mt][0], af[mt][1], af[mt][2], af[mt][3], p);
            }
            uint32_t bf[2][4];
#pragma unroll
            for (int bt = 0; bt < 2; bt++) {
                int nrow = wn * 32 + bt * 16 + (lane & 7) + ((lane >> 4) << 3);
                const __half* p = sw + nrow * XS + k0 + ((lane >> 3) & 1) * 8;
                ldm4(bf[bt][0], bf[bt][1], bf[bt][2], bf[bt][3], p);
            }
#pragma unroll
            for (int mt = 0; mt < 4; mt++)
#pragma unroll
                for (int nt = 0; nt < 4; nt++)
                    mma16816(acc[mt][nt], af[mt],
                             bf[nt >> 1][(nt & 1) * 2], bf[nt >> 1][(nt & 1) * 2 + 1]);
        }
        __syncthreads();
    }

    int gid = lane >> 2, tig = lane & 3;

    if (bias) {
#pragma unroll
        for (int nt = 0; nt < 4; nt++) {
            int col = wn * 32 + nt * 8 + tig * 2;
            float w0 = bias[col], w1 = bias[col + 1];
#pragma unroll
            for (int mt = 0; mt < 4; mt++) {
                acc[mt][nt][0] += w0; acc[mt][nt][1] += w1;
                acc[mt][nt][2] += w0; acc[mt][nt][3] += w1;
            }
        }
    }

    if (w2) {
        if (tid < 128) scbuf[tid] = 0.f;
        __syncthreads();
        float w2v[8];
#pragma unroll
        for (int nt = 0; nt < 4; nt++) {
            int col = wn * 32 + nt * 8 + tig * 2;
            w2v[2 * nt] = w2[col]; w2v[2 * nt + 1] = w2[col + 1];
        }
#pragma unroll
        for (int mt = 0; mt < 4; mt++) {
            float s1 = 0.f, s2 = 0.f;
#pragma unroll
            for (int nt = 0; nt < 4; nt++) {
                s1 += acc[mt][nt][0] * w2v[2 * nt] + acc[mt][nt][1] * w2v[2 * nt + 1];
                s2 += acc[mt][nt][2] * w2v[2 * nt] + acc[mt][nt][3] * w2v[2 * nt + 1];
            }
            s1 += __shfl_xor_sync(0xffffffffu, s1, 1);
            s1 += __shfl_xor_sync(0xffffffffu, s1, 2);
            s2 += __shfl_xor_sync(0xffffffffu, s2, 1);
            s2 += __shfl_xor_sync(0xffffffffu, s2, 2);
            if (tig == 0) {
                atomicAdd(&scbuf[wm * 64 + mt * 16 + gid], s1);
                atomicAdd(&scbuf[wm * 64 + mt * 16 + gid + 8], s2);
            }
        }
        __syncthreads();
        if (tid < 128 && row0 + tid < M) sc[(size_t)(row0 + tid) * scstride] = scbuf[tid];
    }

#pragma unroll
    for (int mt = 0; mt < 4; mt++) {
        int r1 = row0 + wm * 64 + mt * 16 + gid;
        int r2 = r1 + 8;
#pragma unroll
        for (int nt = 0; nt < 4; nt++) {
            int col = wn * 32 + nt * 8 + tig * 2;
            float c0 = acc[mt][nt][0], c1 = acc[mt][nt][1];
            float c2 = acc[mt][nt][2], c3 = acc[mt][nt][3];
            if (Cf) {
                if (r1 < M) *(float2*)(Cf + (size_t)r1 * DIM + col) = make_float2(c0, c1);
                if (r2 < M) *(float2*)(Cf + (size_t)r2 * DIM + col) = make_float2(c2, c3);
            }
            if (Ch) {
                if (r1 < M) *(__half2*)(Ch + (size_t)r1 * DIM + col) = __floats2half2_rn(c0, c1);
                if (r2 < M) *(__half2*)(Ch + (size_t)r2 * DIM + col) = __floats2half2_rn(c2, c3);
            }
        }
    }
}

#define GBN ((N_NODES + 127) / 128)

// ---- modality projections (fp32 inputs, fp16 out), convert fused into loads ----
__global__ __launch_bounds__(256, 2)
void proj_mma_kernel(const float* __restrict__ vis, const float* __restrict__ Wv,
                     const float* __restrict__ bv,
                     const float* __restrict__ txt, const float* __restrict__ Wt,
                     const float* __restrict__ bt) {
    int row0 = blockIdx.x * 128;
    if (blockIdx.z == 0)
        mma_tile<float, float>(vis, N_NODES, VIS_DIM, VIS_DIM, Wv, VIS_DIM, bv,
                               nullptr, g_vf16, nullptr, nullptr, 0, row0);
    else
        mma_tile<float, float>(txt, N_NODES, TXT_DIM, TXT_DIM, Wt, TXT_DIM, bt,
                               nullptr, g_tf16, nullptr, nullptr, 0, row0);
}

// ---- node tables (z=0..5) + relation tables (z=6) ----
__global__ __launch_bounds__(256, 2)
void node_rel_kernel(const float* __restrict__ s_emb, const float* __restrict__ rel_emb,
                     const float* __restrict__ W1s, const float* __restrict__ b1s,
                     const float* __restrict__ w2s,
                     const float* __restrict__ W1v, const float* __restrict__ b1v,
                     const float* __restrict__ w2v,
                     const float* __restrict__ W1t, const float* __restrict__ b1t,
                     const float* __restrict__ w2t) {
    int z = blockIdx.z;
    if (z < 6) {
        int c = z >> 1;          // conv
        int half = z & 1;        // 0=A(dst) 1=B(src)
        const float* W1 = (c == 0) ? W1s : (c == 1) ? W1v : W1t;
        const float* w2 = (c == 0) ? w2s : (c == 1) ? w2v : w2t;
        int row0 = blockIdx.x * 128;
        if (c == 0) {
            if (half == 0)
                mma_tile<float, float>(s_emb, N_NODES, DIM, DIM, W1, 384, nullptr,
                                       g_A[0], nullptr, w2, (float*)g_asc4 + 0, 4, row0);
            else
                mma_tile<float, float>(s_emb, N_NODES, DIM, DIM, W1 + 128, 384, nullptr,
                                       nullptr, g_Bh[0], w2, (float*)g_bsc4 + 0, 4, row0);
        } else {
            const __half* feat = (c == 1) ? g_vf16 : g_tf16;
            if (half == 0)
                mma_tile<__half, float>(feat, N_NODES, DIM, DIM, W1, 384, nullptr,
                                        g_A[c], nullptr, w2, (float*)g_asc4 + c, 4, row0);
            else
                mma_tile<__half, float>(feat, N_NODES, DIM, DIM, W1 + 128, 384, nullptr,
                                        nullptr, g_Bh[c], w2, (float*)g_bsc4 + c, 4, row0);
        }
    } else {
        if (blockIdx.x >= 6) return;
        int c = blockIdx.x >> 1;
        int row0 = (blockIdx.x & 1) * 128;
        const float* W1 = (c == 0) ? W1s : (c == 1) ? W1v : W1t;
        const float* b1 = (c == 0) ? b1s : (c == 1) ? b1v : b1t;
        const float* w2 = (c == 0) ? w2s : (c == 1) ? w2v : w2t;
        mma_tile<float, float>(rel_emb, N_RELS, DIM, DIM, W1 + 256, 384, b1,
                               nullptr, g_Rh[c], w2, (float*)g_rsc4 + c, 4, row0);
    }
}

// ---------------- fused aggregation: half-warp pairing + shuffle-batched logits ----------
// Phase A (per 32-edge batch): each lane computes the logit/exp for ONE edge (1x total).
// Phase B: R12 half-warp pair loop; pk/e values come from __shfl_sync instead of
// redundant recompute. Memory pattern of the accumulate path identical to R12.
__device__ __forceinline__ void accum8(float* acc, float e, uint4 vb, uint4 vr) {
    __half2 h; float2 f;
    h = __hadd2(*(__half2*)&vb.x, *(__half2*)&vr.x); f = __half22float2(h);
    acc[0] += e * f.x; acc[1] += e * f.y;
    h = __hadd2(*(__half2*)&vb.y, *(__half2*)&vr.y); f = __half22float2(h);
    acc[2] += e * f.x; acc[3] += e * f.y;
    h = __hadd2(*(__half2*)&vb.z, *(__half2*)&vr.z); f = __half22float2(h);
    acc[4] += e * f.x; acc[5] += e * f.y;
    h = __hadd2(*(__half2*)&vb.w, *(__half2*)&vr.w); f = __half22float2(h);
    acc[6] += e * f.x; acc[7] += e * f.y;
}

__global__ __launch_bounds__(256)
void aggregate_kernel(const float* __restrict__ alpha_p,
                      const float* __restrict__ gamma_p,
                      float* __restrict__ out) {
    __shared__ float4 s_rsc[N_RELS];
    for (int i = threadIdx.x; i < N_RELS; i += blockDim.x) s_rsc[i] = g_rsc4[i];
    __syncthreads();

    int gw = (blockIdx.x * blockDim.x + threadIdx.x) >> 5;   // node id
    int lane = threadIdx.x & 31;
    if (gw >= N_NODES) return;

    int cnt = g_counts[gw];
    if (lane == 0) g_counts[gw] = 0;       // restore invariant for next replay
    if (cnt > MAXDEG) cnt = MAXDEG;
    const int* bucket = g_bucket + (size_t)gw * MAXDEG;

    float4 av = g_asc4[gw];

    int hw = lane >> 4;        // which edge of the pair
    int hl = lane & 15;        // position within half-warp
    int loff = hl * 8;         // 8 halves per lane

    const __half* B0 = g_Bh[0];
    const __half* B1 = g_Bh[1];
    const __half* B2 = g_Bh[2];
    const __half* R0 = g_Rh[0];
    const __half* R1 = g_Rh[1];
    const __half* R2 = g_Rh[2];

    float acc0[8] = {0, 0, 0, 0, 0, 0, 0, 0};
    float acc1[8] = {0, 0, 0, 0, 0, 0, 0, 0};
    float acc2[8] = {0, 0, 0, 0, 0, 0, 0, 0};
    float z0 = 0.f, z1 = 0.f, z2 = 0.f;

    for (int i0 = 0; i0 < cnt; i0 += 32) {
        int nb = cnt - i0; if (nb > 32) nb = 32;

        // ---- phase A: lane computes exp-weight for edge i0+lane (once per edge) ----
        float e0b = 0.f, e1b = 0.f, e2b = 0.f;
        int pkb = 0;
        if (lane < nb) {
            pkb = bucket[i0 + lane];
            int s = pkb & 0xFFFF;
            int t = pkb >> 16;
            float4 bs = g_bsc4[s];
            float4 rs = s_rsc[t];
            e0b = __expf(lrelu(av.x + bs.x + rs.x));
            e1b = __expf(lrelu(av.y + bs.y + rs.y));
            e2b = __expf(lrelu(av.z + bs.z + rs.z));
        }
        z0 += e0b; z1 += e1b; z2 += e2b;   // per-lane partial; reduced at end

        // ---- phase B: half-warp pair loop, weights via shuffle ----
#pragma unroll 2
        for (int i = 0; i < nb; i += 2) {
            int ei = i + hw;
            bool valid = (ei < nb);
            int sel = valid ? ei : i;
            int pk = __shfl_sync(0xffffffffu, pkb, sel);
            float e0 = __shfl_sync(0xffffffffu, e0b, sel);
            float e1 = __shfl_sync(0xffffffffu, e1b, sel);
            float e2 = __shfl_sync(0xffffffffu, e2b, sel);
            if (!valid) { e0 = 0.f; e1 = 0.f; e2 = 0.f; }
            int s = pk & 0xFFFF;
            int t = pk >> 16;

            uint4 vb0 = *(const uint4*)(B0 + s * DIM + loff);
            uint4 vr0 = *(const uint4*)(R0 + t * DIM + loff);
            uint4 vb1 = *(const uint4*)(B1 + s * DIM + loff);
            uint4 vr1 = *(const uint4*)(R1 + t * DIM + loff);
            uint4 vb2 = *(const uint4*)(B2 + s * DIM + loff);
            uint4 vr2 = *(const uint4*)(R2 + t * DIM + loff);

            accum8(acc0, e0, vb0, vr0);
            accum8(acc1, e1, vb1, vr1);
            accum8(acc2, e2, vb2, vr2);
        }
    }

    // combine the two half-warps (each covered the same dims, different edges)
#pragma unroll
    for (int k = 0; k < 8; k++) {
        acc0[k] += __shfl_xor_sync(0xffffffffu, acc0[k], 16);
        acc1[k] += __shfl_xor_sync(0xffffffffu, acc1[k], 16);
        acc2[k] += __shfl_xor_sync(0xffffffffu, acc2[k], 16);
    }
    // z: full-warp reduction (per-lane partials from phase A)
#pragma unroll
    for (int o = 16; o > 0; o >>= 1) {
        z0 += __shfl_xor_sync(0xffffffffu, z0, o);
        z1 += __shfl_xor_sync(0xffffffffu, z1, o);
        z2 += __shfl_xor_sync(0xffffffffu, z2, o);
    }

    float al = *alpha_p, ga = *gamma_p;
    float cs = 1.f - al - ga;
    int col = hl * 8 + hw * 4;           // this lane writes 4 dims
    int base = hw * 4;                   // which 4 of the lane's 8 accumulated dims
    float4 o = {0, 0, 0, 0};
    if (cnt > 0) {
        float4 A0 = *(const float4*)(&g_A[0][gw * DIM + col]);
        float4 A1 = *(const float4*)(&g_A[1][gw * DIM + col]);
        float4 A2 = *(const float4*)(&g_A[2][gw * DIM + col]);
        float iz0 = 1.f / z0, iz1 = 1.f / z1, iz2 = 1.f / z2;
        o.x = cs * lrelu(A0.x + acc0[base + 0] * iz0) + al * lrelu(A1.x + acc1[base + 0] * iz1) + ga * lrelu(A2.x + acc2[base + 0] * iz2);
        o.y = cs * lrelu(A0.y + acc0[base + 1] * iz0) + al * lrelu(A1.y + acc1[base + 1] * iz1) + ga * lrelu(A2.y + acc2[base + 1] * iz2);
        o.z = cs * lrelu(A0.z + acc0[base + 2] * iz0) + al * lrelu(A1.z + acc1[base + 2] * iz1) + ga * lrelu(A2.z + acc2[base + 2] * iz2);
        o.w = cs * lrelu(A0.w + acc0[base + 3] * iz0) + al * lrelu(A1.w + acc1[base + 3] * iz1) + ga * lrelu(A2.w + acc2[base + 3] * iz2);
    }
    *(float4*)(out + (size_t)gw * DIM + col) = o;
}

// ---------------- host launcher ----------------
extern "C" void kernel_launch(void* const* d_in, const int* in_sizes, int n_in,
                              void* d_out, int out_size) {
    const int*   edge_index = (const int*)d_in[1];   // [2, E]
    const int*   edge_type  = (const int*)d_in[2];
    const float* visual     = (const float*)d_in[3];
    const float* textual    = (const float*)d_in[4];
    const float* s_emb      = (const float*)d_in[5];
    const float* rel_emb    = (const float*)d_in[6];
    const float* W1_s = (const float*)d_in[7];
    const float* b1_s = (const float*)d_in[8];
    const float* w2_s = (const float*)d_in[9];
    const float* W1_v = (const float*)d_in[10];
    const float* b1_v = (const float*)d_in[11];
    const float* w2_v = (const float*)d_in[12];
    const float* W1_t = (const float*)d_in[13];
    const float* b1_t = (const float*)d_in[14];
    const float* w2_t = (const float*)d_in[15];
    const float* Wv = (const float*)d_in[16];
    const float* bv = (const float*)d_in[17];
    const float* Wt = (const float*)d_in[18];
    const float* bt = (const float*)d_in[19];
    const float* alpha = (const float*)d_in[20];
    const float* gamma = (const float*)d_in[21];
    float* out = (float*)d_out;

    const int* src = edge_index;
    const int* dst = edge_index + N_EDGES;

    // launch 0: bucket scatter (lightweight, full occupancy)
    scatter_kernel<<<(N_EDGES / 2 + 255) / 256, 256>>>(src, dst, edge_type);

    // launch 1: modality projections (fp32 inputs converted in-register)
    proj_mma_kernel<<<dim3(GBN, 1, 2), 256>>>(visual, Wv, bv, textual, Wt, bt);

    // launch 2: node tables (z=0..5) + relation tables (z=6)
    node_rel_kernel<<<dim3(GBN, 1, 7), 256>>>(
        s_emb, rel_emb, W1_s, b1_s, w2_s, W1_v, b1_v, w2_v, W1_t, b1_t, w2_t);

    // launch 3: fused aggregation, 1 warp per node, shuffle-batched logits
    aggregate_kernel<<<1250, 256>>>(alpha, gamma, out);
}